// round 1
// baseline (speedup 1.0000x reference)
#include <cuda_runtime.h>

#define HID   128
#define S     4      // samples per warp per iteration
#define W2S   132    // padded row stride for W2 in smem (bank-conflict mitigation)
#define NWARP 8
#define NTHR  256

// exact identity tanh(x) = 1 - 2/(exp(2x)+1); error ~1e-7 abs from __expf
__device__ __forceinline__ float ftanh(float x) {
    float e = __expf(2.0f * x);
    return 1.0f - __fdividef(2.0f, e + 1.0f);
}

__global__ void __launch_bounds__(NTHR, 2)
lnn_kernel(const float* __restrict__ X,
           const float* __restrict__ W1, const float* __restrict__ b1,
           const float* __restrict__ W2, const float* __restrict__ b2,
           const float* __restrict__ W3,
           float* __restrict__ out, int B)
{
    extern __shared__ float sm[];
    float* sW2  = sm;                    // HID * W2S
    float* sW1  = sW2 + HID * W2S;       // 4 * HID
    float* sb1  = sW1 + 4 * HID;         // HID
    float* sb2  = sb1 + HID;             // HID
    float* sW3  = sb2 + HID;             // HID
    float* bufs = sW3 + HID;             // NWARP * 2 * HID * S

    const int tid = threadIdx.x;

    // cooperative weight staging
    for (int idx = tid; idx < HID * HID; idx += NTHR) {
        int r = idx >> 7, c = idx & 127;
        sW2[r * W2S + c] = W2[idx];
    }
    for (int idx = tid; idx < 4 * HID; idx += NTHR) sW1[idx] = W1[idx];
    for (int idx = tid; idx < HID; idx += NTHR) {
        sb1[idx] = b1[idx];
        sb2[idx] = b2[idx];
        sW3[idx] = W3[idx];
    }
    __syncthreads();

    const int warp = tid >> 5;
    const int lane = tid & 31;
    const int k0   = lane * 4;          // this lane owns hidden units k0..k0+3
    float* h1b = bufs + warp * (2 * HID * S);   // layout [j][s], float4 over s
    float* g2b = h1b + HID * S;                 // layout [k][s], float4 over s

    const int gw    = blockIdx.x * NWARP + warp;
    const int nwTot = gridDim.x * NWARP;

    for (int base = gw * S; base < B; base += nwTot * S) {
        // ---- load S samples (broadcast to all lanes) ----
        float4 xs[S];
        #pragma unroll
        for (int s = 0; s < S; s++)
            xs[s] = reinterpret_cast<const float4*>(X)[base + s];

        float s1[S], c1[S], s2[S], c2[S];
        #pragma unroll
        for (int s = 0; s < S; s++) {
            __sincosf(xs[s].x, &s1[s], &c1[s]);
            __sincosf(xs[s].y, &s2[s], &c2[s]);
        }

        // ---- layer 1: z1_k = feat . W1[:,k],  h1 = tanh(z1) ----
        float h1r[S][4];
        #pragma unroll
        for (int r = 0; r < 4; r++) {
            const int k = k0 + r;
            const float a0 = sW1[k], a1 = sW1[HID + k];
            const float a2 = sW1[2 * HID + k], a3 = sW1[3 * HID + k];
            const float bb = sb1[k];
            #pragma unroll
            for (int s = 0; s < S; s++) {
                float z = bb;
                z = fmaf(s1[s], a0, z);
                z = fmaf(c1[s], a1, z);
                z = fmaf(s2[s], a2, z);
                z = fmaf(c2[s], a3, z);
                h1r[s][r] = ftanh(z);
            }
        }
        // stage h1 as [j][s] (float4 over s)
        #pragma unroll
        for (int r = 0; r < 4; r++) {
            reinterpret_cast<float4*>(h1b)[k0 + r] =
                make_float4(h1r[0][r], h1r[1][r], h1r[2][r], h1r[3][r]);
        }
        __syncwarp();

        // ---- layer 2: z2_k = sum_j h1_j * W2[j,k] ----
        float acc[S][4];
        #pragma unroll
        for (int r = 0; r < 4; r++) {
            const float bb = sb2[k0 + r];
            #pragma unroll
            for (int s = 0; s < S; s++) acc[s][r] = bb;
        }
        #pragma unroll 4
        for (int j = 0; j < HID; j++) {
            const float4 h = reinterpret_cast<const float4*>(h1b)[j];
            const float4 w = *reinterpret_cast<const float4*>(&sW2[j * W2S + k0]);
            acc[0][0] = fmaf(h.x, w.x, acc[0][0]);
            acc[0][1] = fmaf(h.x, w.y, acc[0][1]);
            acc[0][2] = fmaf(h.x, w.z, acc[0][2]);
            acc[0][3] = fmaf(h.x, w.w, acc[0][3]);
            acc[1][0] = fmaf(h.y, w.x, acc[1][0]);
            acc[1][1] = fmaf(h.y, w.y, acc[1][1]);
            acc[1][2] = fmaf(h.y, w.z, acc[1][2]);
            acc[1][3] = fmaf(h.y, w.w, acc[1][3]);
            acc[2][0] = fmaf(h.z, w.x, acc[2][0]);
            acc[2][1] = fmaf(h.z, w.y, acc[2][1]);
            acc[2][2] = fmaf(h.z, w.z, acc[2][2]);
            acc[2][3] = fmaf(h.z, w.w, acc[2][3]);
            acc[3][0] = fmaf(h.w, w.x, acc[3][0]);
            acc[3][1] = fmaf(h.w, w.y, acc[3][1]);
            acc[3][2] = fmaf(h.w, w.z, acc[3][2]);
            acc[3][3] = fmaf(h.w, w.w, acc[3][3]);
        }

        // ---- g2_k = W3_k * (1 - h2_k^2), staged as [k][s] ----
        #pragma unroll
        for (int r = 0; r < 4; r++) {
            const float wk = sW3[k0 + r];
            float g[S];
            #pragma unroll
            for (int s = 0; s < S; s++) {
                const float t = ftanh(acc[s][r]);
                g[s] = wk * (1.0f - t * t);
            }
            reinterpret_cast<float4*>(g2b)[k0 + r] =
                make_float4(g[0], g[1], g[2], g[3]);
        }
        __syncwarp();

        // ---- backward: g1_j = (1-h1_j^2) * sum_k W2[j,k] * g2_k ----
        float gacc[S][4];
        #pragma unroll
        for (int s = 0; s < S; s++)
            #pragma unroll
            for (int r = 0; r < 4; r++) gacc[s][r] = 0.0f;

        #pragma unroll 2
        for (int kk = 0; kk < HID; kk += 4) {
            const float4 gA = reinterpret_cast<const float4*>(g2b)[kk + 0];
            const float4 gB = reinterpret_cast<const float4*>(g2b)[kk + 1];
            const float4 gC = reinterpret_cast<const float4*>(g2b)[kk + 2];
            const float4 gD = reinterpret_cast<const float4*>(g2b)[kk + 3];
            #pragma unroll
            for (int r = 0; r < 4; r++) {
                const float4 w =
                    *reinterpret_cast<const float4*>(&sW2[(k0 + r) * W2S + kk]);
                gacc[0][r] = fmaf(w.x, gA.x, gacc[0][r]);
                gacc[0][r] = fmaf(w.y, gB.x, gacc[0][r]);
                gacc[0][r] = fmaf(w.z, gC.x, gacc[0][r]);
                gacc[0][r] = fmaf(w.w, gD.x, gacc[0][r]);
                gacc[1][r] = fmaf(w.x, gA.y, gacc[1][r]);
                gacc[1][r] = fmaf(w.y, gB.y, gacc[1][r]);
                gacc[1][r] = fmaf(w.z, gC.y, gacc[1][r]);
                gacc[1][r] = fmaf(w.w, gD.y, gacc[1][r]);
                gacc[2][r] = fmaf(w.x, gA.z, gacc[2][r]);
                gacc[2][r] = fmaf(w.y, gB.z, gacc[2][r]);
                gacc[2][r] = fmaf(w.z, gC.z, gacc[2][r]);
                gacc[2][r] = fmaf(w.w, gD.z, gacc[2][r]);
                gacc[3][r] = fmaf(w.x, gA.w, gacc[3][r]);
                gacc[3][r] = fmaf(w.y, gB.w, gacc[3][r]);
                gacc[3][r] = fmaf(w.z, gC.w, gacc[3][r]);
                gacc[3][r] = fmaf(w.w, gD.w, gacc[3][r]);
            }
        }

        // ---- g_feat partials: pf[i][s] = sum_{j in lane} W1[i,j] * g1_j ----
        float pf[4][S];
        #pragma unroll
        for (int i = 0; i < 4; i++)
            #pragma unroll
            for (int s = 0; s < S; s++) pf[i][s] = 0.0f;

        #pragma unroll
        for (int r = 0; r < 4; r++) {
            const int j = k0 + r;
            const float a0 = sW1[j], a1 = sW1[HID + j];
            const float a2 = sW1[2 * HID + j], a3 = sW1[3 * HID + j];
            #pragma unroll
            for (int s = 0; s < S; s++) {
                const float h = h1r[s][r];
                const float g1 = (1.0f - h * h) * gacc[s][r];
                pf[0][s] = fmaf(a0, g1, pf[0][s]);
                pf[1][s] = fmaf(a1, g1, pf[1][s]);
                pf[2][s] = fmaf(a2, g1, pf[2][s]);
                pf[3][s] = fmaf(a3, g1, pf[3][s]);
            }
        }

        // butterfly reduce over the warp: every lane ends with full sums
        #pragma unroll
        for (int off = 16; off > 0; off >>= 1) {
            #pragma unroll
            for (int i = 0; i < 4; i++)
                #pragma unroll
                for (int s = 0; s < S; s++)
                    pf[i][s] += __shfl_xor_sync(0xffffffffu, pf[i][s], off);
        }

        // ---- analytic closure + 2x2 solve, lane s handles sample s ----
        if (lane < S) {
            const int s = lane;
            const float w1v = xs[s].z, w2v = xs[s].w;
            const float sd = s1[s] * c2[s] - c1[s] * s2[s];   // sin(t1-t2)
            const float cd = c1[s] * c2[s] + s1[s] * s2[s];   // cos(t1-t2)
            const float dV1 = pf[0][s] * c1[s] - pf[1][s] * s1[s];
            const float dV2 = pf[2][s] * c2[s] - pf[3][s] * s2[s];
            const float dw  = w2v - w1v;
            const float rhs1 = -w1v * w2v * sd - dV1 - w2v * sd * dw;
            const float rhs2 =  w1v * w2v * sd - dV2 - w1v * sd * dw;
            const float det = 2.0f - cd * cd;                 // in [1,2]
            const float inv = __fdividef(1.0f, det);
            const float q1 = (rhs1 - cd * rhs2) * inv;
            const float q2 = (2.0f * rhs2 - cd * rhs1) * inv;
            reinterpret_cast<float4*>(out)[base + s] =
                make_float4(w1v, w2v, q1, q2);
        }
    }
}

extern "C" void kernel_launch(void* const* d_in, const int* in_sizes, int n_in,
                              void* d_out, int out_size)
{
    const float* X  = (const float*)d_in[0];
    const float* W1 = (const float*)d_in[1];
    const float* b1 = (const float*)d_in[2];
    const float* W2 = (const float*)d_in[3];
    const float* b2 = (const float*)d_in[4];
    const float* W3 = (const float*)d_in[5];
    // d_in[6] = b3: V's value never affects gradients -> unused
    float* out = (float*)d_out;
    const int B = in_sizes[0] / 4;

    const size_t smem = (size_t)(HID * W2S + 4 * HID + 3 * HID +
                                 NWARP * 2 * HID * S) * sizeof(float);
    cudaFuncSetAttribute(lnn_kernel,
                         cudaFuncAttributeMaxDynamicSharedMemorySize,
                         (int)smem);
    lnn_kernel<<<296, NTHR, smem>>>(X, W1, b1, W2, b2, W3, out, B);
}

// round 2
// speedup vs baseline: 1.7855x; 1.7855x over previous
#include <cuda_runtime.h>

#define HID   128
#define S     4
#define NWARP 16
#define NTHR  512

// exact identity tanh(x) = 1 - 2/(exp(2x)+1)
__device__ __forceinline__ float ftanh(float x) {
    float e = __expf(2.0f * x);
    return 1.0f - __fdividef(2.0f, e + 1.0f);
}

// packed fp32x2 FMA (SASS FFMA2): d = a*b + c elementwise on 2 floats
__device__ __forceinline__ unsigned long long ffma2(unsigned long long a,
                                                    unsigned long long b,
                                                    unsigned long long c) {
    unsigned long long d;
    asm("fma.rn.f32x2 %0, %1, %2, %3;" : "=l"(d) : "l"(a), "l"(b), "l"(c));
    return d;
}

__device__ __forceinline__ float hadd2(unsigned long long v) {
    float lo, hi;
    asm("mov.b64 {%0, %1}, %2;" : "=f"(lo), "=f"(hi) : "l"(v));
    return lo + hi;
}

__global__ void __launch_bounds__(NTHR, 1)
lnn_kernel(const float* __restrict__ X,
           const float* __restrict__ W1, const float* __restrict__ b1,
           const float* __restrict__ W2, const float* __restrict__ b2,
           const float* __restrict__ W3,
           float* __restrict__ out, int B)
{
    extern __shared__ float sm[];
    float* sW2F = sm;                  // [k][j] swizzled (forward)
    float* sW2B = sW2F + HID * HID;    // [j][k] swizzled (backward)
    float* sW1  = sW2B + HID * HID;    // 4*128
    float* sb1  = sW1 + 4 * HID;
    float* sb2  = sb1 + HID;
    float* sW3  = sb2 + HID;
    float* bufs = sW3 + HID;           // NWARP * 2 * S * HID

    const int tid = threadIdx.x;

    // stage weights; swizzle: chunk c' = c ^ ((row>>2)&31), 16B granularity
    for (int idx = tid; idx < HID * HID; idx += NTHR) {
        const int j = idx >> 7, k = idx & 127;
        const float v = W2[idx];
        sW2F[k * HID + ((((j >> 2) ^ (k >> 2)) & 31) << 2) + (j & 3)] = v;
        sW2B[j * HID + ((((k >> 2) ^ (j >> 2)) & 31) << 2) + (k & 3)] = v;
    }
    for (int idx = tid; idx < 4 * HID; idx += NTHR) sW1[idx] = W1[idx];
    for (int idx = tid; idx < HID; idx += NTHR) {
        sb1[idx] = b1[idx];
        sb2[idx] = b2[idx];
        sW3[idx] = W3[idx];
    }
    __syncthreads();

    const int warp = tid >> 5;
    const int lane = tid & 31;
    const int u0   = lane << 2;          // this lane owns hidden units u0..u0+3
    float* h1b = bufs + warp * (2 * S * HID);   // [s][128]
    float* g2b = h1b + S * HID;                 // [s][128]

    // lane-owned swizzled row bases
    const float* wF[4];
    const float* wB[4];
    #pragma unroll
    for (int r = 0; r < 4; r++) {
        wF[r] = sW2F + (u0 + r) * HID;
        wB[r] = sW2B + (u0 + r) * HID;
    }

    const int gw    = blockIdx.x * NWARP + warp;
    const int nwTot = gridDim.x * NWARP;

    for (int base = gw * S; base < B; base += nwTot * S) {
        float4 xs[S];
        #pragma unroll
        for (int s = 0; s < S; s++)
            xs[s] = reinterpret_cast<const float4*>(X)[base + s];

        float s1[S], c1[S], s2[S], c2[S];
        #pragma unroll
        for (int s = 0; s < S; s++) {
            __sincosf(xs[s].x, &s1[s], &c1[s]);
            __sincosf(xs[s].y, &s2[s], &c2[s]);
        }

        // ---- layer 1 ----
        float h1r[S][4];
        #pragma unroll
        for (int r = 0; r < 4; r++) {
            const int u = u0 + r;
            const float a0 = sW1[u], a1 = sW1[HID + u];
            const float a2 = sW1[2 * HID + u], a3 = sW1[3 * HID + u];
            const float bb = sb1[u];
            #pragma unroll
            for (int s = 0; s < S; s++) {
                float z = bb;
                z = fmaf(s1[s], a0, z);
                z = fmaf(c1[s], a1, z);
                z = fmaf(s2[s], a2, z);
                z = fmaf(c2[s], a3, z);
                h1r[s][r] = ftanh(z);
            }
        }
        __syncwarp();
        #pragma unroll
        for (int s = 0; s < S; s++)
            *reinterpret_cast<float4*>(&h1b[s * HID + u0]) =
                make_float4(h1r[s][0], h1r[s][1], h1r[s][2], h1r[s][3]);
        __syncwarp();

        // ---- layer 2 forward: z2[k] = sum_j h[j] * W2[j][k]  (pairs over j) ----
        unsigned long long acc2[S][4];
        #pragma unroll
        for (int s = 0; s < S; s++)
            #pragma unroll
            for (int r = 0; r < 4; r++) acc2[s][r] = 0ull;

        #pragma unroll 2
        for (int jc = 0; jc < 32; jc++) {
            const int off = ((jc ^ lane) & 31) << 2;
            ulonglong2 wv[4];
            #pragma unroll
            for (int r = 0; r < 4; r++)
                wv[r] = *reinterpret_cast<const ulonglong2*>(wF[r] + off);
            ulonglong2 hv[S];
            #pragma unroll
            for (int s = 0; s < S; s++)
                hv[s] = *reinterpret_cast<const ulonglong2*>(&h1b[s * HID + (jc << 2)]);
            #pragma unroll
            for (int s = 0; s < S; s++)
                #pragma unroll
                for (int r = 0; r < 4; r++) {
                    acc2[s][r] = ffma2(hv[s].x, wv[r].x, acc2[s][r]);
                    acc2[s][r] = ffma2(hv[s].y, wv[r].y, acc2[s][r]);
                }
        }

        // ---- g2[k] = W3[k]*(1 - tanh(z2)^2) ----
        __syncwarp();
        #pragma unroll
        for (int s = 0; s < S; s++) {
            float g[4];
            #pragma unroll
            for (int r = 0; r < 4; r++) {
                const float z = hadd2(acc2[s][r]) + sb2[u0 + r];
                const float t = ftanh(z);
                g[r] = sW3[u0 + r] * (1.0f - t * t);
            }
            *reinterpret_cast<float4*>(&g2b[s * HID + u0]) =
                make_float4(g[0], g[1], g[2], g[3]);
        }
        __syncwarp();

        // ---- backward: g1[j] = (1-h^2) * sum_k W2[j][k] * g2[k]  (pairs over k) ----
        unsigned long long gacc2[S][4];
        #pragma unroll
        for (int s = 0; s < S; s++)
            #pragma unroll
            for (int r = 0; r < 4; r++) gacc2[s][r] = 0ull;

        #pragma unroll 2
        for (int kc = 0; kc < 32; kc++) {
            const int off = ((kc ^ lane) & 31) << 2;
            ulonglong2 wv[4];
            #pragma unroll
            for (int r = 0; r < 4; r++)
                wv[r] = *reinterpret_cast<const ulonglong2*>(wB[r] + off);
            ulonglong2 gv[S];
            #pragma unroll
            for (int s = 0; s < S; s++)
                gv[s] = *reinterpret_cast<const ulonglong2*>(&g2b[s * HID + (kc << 2)]);
            #pragma unroll
            for (int s = 0; s < S; s++)
                #pragma unroll
                for (int r = 0; r < 4; r++) {
                    gacc2[s][r] = ffma2(gv[s].x, wv[r].x, gacc2[s][r]);
                    gacc2[s][r] = ffma2(gv[s].y, wv[r].y, gacc2[s][r]);
                }
        }

        // ---- feature-gradient partials ----
        float pf[4][S];
        #pragma unroll
        for (int i = 0; i < 4; i++)
            #pragma unroll
            for (int s = 0; s < S; s++) pf[i][s] = 0.0f;

        #pragma unroll
        for (int r = 0; r < 4; r++) {
            const int j = u0 + r;
            const float a0 = sW1[j], a1 = sW1[HID + j];
            const float a2 = sW1[2 * HID + j], a3 = sW1[3 * HID + j];
            #pragma unroll
            for (int s = 0; s < S; s++) {
                const float h  = h1r[s][r];
                const float g1 = (1.0f - h * h) * hadd2(gacc2[s][r]);
                pf[0][s] = fmaf(a0, g1, pf[0][s]);
                pf[1][s] = fmaf(a1, g1, pf[1][s]);
                pf[2][s] = fmaf(a2, g1, pf[2][s]);
                pf[3][s] = fmaf(a3, g1, pf[3][s]);
            }
        }

        #pragma unroll
        for (int off = 16; off > 0; off >>= 1)
            #pragma unroll
            for (int i = 0; i < 4; i++)
                #pragma unroll
                for (int s = 0; s < S; s++)
                    pf[i][s] += __shfl_xor_sync(0xffffffffu, pf[i][s], off);

        if (lane < S) {
            const int s = lane;
            const float w1v = xs[s].z, w2v = xs[s].w;
            const float sd = s1[s] * c2[s] - c1[s] * s2[s];
            const float cd = c1[s] * c2[s] + s1[s] * s2[s];
            const float dV1 = pf[0][s] * c1[s] - pf[1][s] * s1[s];
            const float dV2 = pf[2][s] * c2[s] - pf[3][s] * s2[s];
            const float dw  = w2v - w1v;
            const float rhs1 = -w1v * w2v * sd - dV1 - w2v * sd * dw;
            const float rhs2 =  w1v * w2v * sd - dV2 - w1v * sd * dw;
            const float det = 2.0f - cd * cd;
            const float inv = __fdividef(1.0f, det);
            const float q1 = (rhs1 - cd * rhs2) * inv;
            const float q2 = (2.0f * rhs2 - cd * rhs1) * inv;
            reinterpret_cast<float4*>(out)[base + s] =
                make_float4(w1v, w2v, q1, q2);
        }
    }
}

extern "C" void kernel_launch(void* const* d_in, const int* in_sizes, int n_in,
                              void* d_out, int out_size)
{
    const float* X  = (const float*)d_in[0];
    const float* W1 = (const float*)d_in[1];
    const float* b1 = (const float*)d_in[2];
    const float* W2 = (const float*)d_in[3];
    const float* b2 = (const float*)d_in[4];
    const float* W3 = (const float*)d_in[5];
    float* out = (float*)d_out;
    const int B = in_sizes[0] / 4;

    const size_t smem = (size_t)(2 * HID * HID + 4 * HID + 3 * HID +
                                 NWARP * 2 * S * HID) * sizeof(float);
    cudaFuncSetAttribute(lnn_kernel,
                         cudaFuncAttributeMaxDynamicSharedMemorySize,
                         (int)smem);
    lnn_kernel<<<296, NTHR, smem>>>(X, W1, b1, W2, b2, W3, out, B);
}